// round 4
// baseline (speedup 1.0000x reference)
#include <cuda_runtime.h>

#define BB 512
#define SS 512
#define EE 64
#define PADs 0
#define BOSs 1
#define EOSs 2
#define NORM_EVERY 4

// Scratch (device globals — allocation-free rule)
__device__ float g_logz[BB];
__device__ float g_score[BB];

// ---------------------------------------------------------------------------
// Forward pass: one block (64 threads) per sequence.
// Thread j owns state j; M column exp(T[:,j]) lives in registers.
// Linear-domain recursion with rescaling every NORM_EVERY steps.
// ---------------------------------------------------------------------------
__global__ __launch_bounds__(EE) void crf_forward(
    const float* __restrict__ em,        // [B,S,E]
    const float* __restrict__ T,         // [E,E]
    const int* __restrict__ mask)        // [B,S] (bool materialized as int32)
{
    __shared__ __align__(16) float abuf[2][EE];
    __shared__ float red[2];

    const int b    = blockIdx.x;
    const int j    = threadIdx.x;
    const int lane = j & 31;
    const int w    = j >> 5;

    // M column (exp of transitions INTO state j). exp(-10000) underflows to 0 — exact.
    float Mcol[EE];
#pragma unroll
    for (int i = 0; i < EE; i++) Mcol[i] = __expf(T[i * EE + j]);

    const float* emb = em + (size_t)b * SS * EE;
    const int*   mb  = mask + (size_t)b * SS;

    // alpha0 = exp(T[BOS,j] + em[0,j]); normalize immediately.
    float a    = __expf(T[BOSs * EE + j] + emb[j]);
    float logC = 0.f;
    {
        float s = a;
#pragma unroll
        for (int o = 16; o > 0; o >>= 1) s += __shfl_xor_sync(0xffffffffu, s, o);
        if (lane == 0) red[w] = s;
        __syncthreads();
        s = red[0] + red[1];
        a *= 1.0f / s;
        logC += __logf(s);
        abuf[0][j] = a;
        __syncthreads();
    }

    int cur = 0;
    float em_next = emb[EE + j];  // prefetch t=1 emission

    for (int t = 1; t < SS; t++) {
        const float emv = em_next;
        if (t + 1 < SS) em_next = emb[(size_t)(t + 1) * EE + j];
        const int m = mb[t];

        // v_j = sum_i a_i * M[i][j]  (broadcast LDS.128, 4 independent accumulators)
        const float4* av = reinterpret_cast<const float4*>(abuf[cur]);
        float acc0 = 0.f, acc1 = 0.f, acc2 = 0.f, acc3 = 0.f;
#pragma unroll
        for (int i = 0; i < EE / 4; i++) {
            const float4 v4 = av[i];
            acc0 = fmaf(v4.x, Mcol[4 * i + 0], acc0);
            acc1 = fmaf(v4.y, Mcol[4 * i + 1], acc1);
            acc2 = fmaf(v4.z, Mcol[4 * i + 2], acc2);
            acc3 = fmaf(v4.w, Mcol[4 * i + 3], acc3);
        }
        float v = (acc0 + acc1) + (acc2 + acc3);
        v *= __expf(emv);

        if (m) a = v;  // masked update: keep old alpha where mask is false

        // Periodic rescale: divide by sum, accumulate log.
        if ((t & (NORM_EVERY - 1)) == 0) {
            float s = a;
#pragma unroll
            for (int o = 16; o > 0; o >>= 1) s += __shfl_xor_sync(0xffffffffu, s, o);
            if (lane == 0) red[w] = s;
            __syncthreads();
            s = red[0] + red[1];
            a *= 1.0f / s;
            logC += __logf(s);
        }

        const int nxt = cur ^ 1;
        abuf[nxt][j] = a;
        __syncthreads();
        cur = nxt;
    }

    // log_z = logC + log( sum_j a_j * exp(T[j,EOS]) )
    {
        float z = a * __expf(T[j * EE + EOSs]);
#pragma unroll
        for (int o = 16; o > 0; o >>= 1) z += __shfl_xor_sync(0xffffffffu, z, o);
        if (lane == 0) red[w] = z;
        __syncthreads();
        if (j == 0) g_logz[b] = logC + __logf(red[0] + red[1]);
    }
}

// ---------------------------------------------------------------------------
// Path score: one warp per sequence.
// ---------------------------------------------------------------------------
__global__ __launch_bounds__(256) void crf_score(
    const float* __restrict__ em,
    const float* __restrict__ T,
    const int* __restrict__ ent,
    const int* __restrict__ mask)
{
    const int warp = blockIdx.x * (blockDim.x >> 5) + (threadIdx.x >> 5);
    const int lane = threadIdx.x & 31;
    if (warp >= BB) return;
    const int b = warp;

    const float* emb = em + (size_t)b * SS * EE;
    const int*   eb  = ent + (size_t)b * SS;
    const int*   mb  = mask + (size_t)b * SS;

    float acc  = 0.f;
    int nvalid = 0;
    for (int t = lane; t < SS; t += 32) {
        const int e = eb[t];
        const int m = mb[t];
        nvalid += m ? 1 : 0;
        if (t >= 1 && m) {
            const int ep = eb[t - 1];
            acc += emb[(size_t)t * EE + e] + T[ep * EE + e];
        }
    }
#pragma unroll
    for (int o = 16; o > 0; o >>= 1) {
        acc    += __shfl_xor_sync(0xffffffffu, acc, o);
        nvalid += __shfl_xor_sync(0xffffffffu, nvalid, o);
    }
    if (lane == 0) {
        const int e0   = eb[0];
        const int last = eb[nvalid - 1];
        acc += T[BOSs * EE + e0] + emb[e0] + T[last * EE + EOSs];
        g_score[b] = acc;
    }
}

// ---------------------------------------------------------------------------
// Final reduction: nll = mean(log_z - score)
// ---------------------------------------------------------------------------
__global__ __launch_bounds__(512) void crf_reduce(float* __restrict__ out) {
    __shared__ float sh[BB];
    const int i = threadIdx.x;
    sh[i] = g_logz[i] - g_score[i];
    __syncthreads();
#pragma unroll
    for (int s = BB / 2; s > 0; s >>= 1) {
        if (i < s) sh[i] += sh[i + s];
        __syncthreads();
    }
    if (i == 0) out[0] = sh[0] / (float)BB;
}

extern "C" void kernel_launch(void* const* d_in, const int* in_sizes, int n_in,
                              void* d_out, int out_size) {
    const float* emissions   = (const float*)d_in[0];
    const float* transitions = (const float*)d_in[1];
    const int*   entities    = (const int*)d_in[2];
    const int*   mask        = (const int*)d_in[3];
    float* out               = (float*)d_out;

    crf_score<<<BB / 8, 256>>>(emissions, transitions, entities, mask);
    crf_forward<<<BB, EE>>>(emissions, transitions, mask);
    crf_reduce<<<1, BB>>>(out);
}

// round 6
// speedup vs baseline: 1.0812x; 1.0812x over previous
#include <cuda_runtime.h>

#define BB 512
#define SS 512
#define EE 64
#define BOSs 1
#define EOSs 2
#define NE 8   // normalize every 8 steps (growth bounded well inside fp32 range)

typedef unsigned long long u64;

// Scratch (device globals — allocation-free rule)
__device__ float g_val[BB];   // per-sequence (log_z - score)

// ---- packed fp32x2 helpers (sm_103a FFMA2 pipe, PTX-only) ----
__device__ __forceinline__ u64 ffma2(u64 a, u64 b, u64 c) {
    u64 d;
    asm("fma.rn.f32x2 %0, %1, %2, %3;" : "=l"(d) : "l"(a), "l"(b), "l"(c));
    return d;
}
__device__ __forceinline__ u64 fadd2(u64 a, u64 b) {
    u64 d;
    asm("add.rn.f32x2 %0, %1, %2;" : "=l"(d) : "l"(a), "l"(b));
    return d;
}
__device__ __forceinline__ u64 pack2(float lo, float hi) {
    u64 d;
    asm("mov.b64 %0, {%1, %2};" : "=l"(d) : "f"(lo), "f"(hi));
    return d;
}
__device__ __forceinline__ float2 unpack2(u64 v) {
    float lo, hi;
    asm("mov.b64 {%0, %1}, %2;" : "=f"(lo), "=f"(hi) : "l"(v));
    float2 r; r.x = lo; r.y = hi; return r;
}

// ---------------------------------------------------------------------------
// Fused forward + path score: one block (64 threads) per sequence.
// Thread j owns state j; packed exp(T) column pairs live in 32 b64 registers.
// Linear-domain recursion, deferred rescale every NE steps, ONE barrier/step.
// ---------------------------------------------------------------------------
__global__ __launch_bounds__(EE) void crf_fused(
    const float* __restrict__ em,     // [B,S,E]
    const float* __restrict__ T,      // [E,E]
    const int*   __restrict__ ent,    // [B,S]
    const int*   __restrict__ mask)   // [B,S] (bool as int32)
{
    __shared__ __align__(16) float abuf[2][EE];
    __shared__ float red[2];          // alpha-sum halves (deferred scale)
    __shared__ float redz[2];         // final z halves
    __shared__ float reds[2];         // score halves
    __shared__ __align__(16) float Tsh[EE * EE];
    __shared__ __align__(16) int   esh[SS];
    __shared__ __align__(16) int   msh[SS];

    const int b    = blockIdx.x;
    const int j    = threadIdx.x;
    const int lane = j & 31;
    const int w    = j >> 5;

    // Stage T, entities, mask into shared (coalesced vector loads).
    {
        const float4* Tg = reinterpret_cast<const float4*>(T);
        float4*       Ts = reinterpret_cast<float4*>(Tsh);
        for (int i = j; i < EE * EE / 4; i += EE) Ts[i] = Tg[i];
        const int4* eg = reinterpret_cast<const int4*>(ent + (size_t)b * SS);
        const int4* mg = reinterpret_cast<const int4*>(mask + (size_t)b * SS);
        int4* es = reinterpret_cast<int4*>(esh);
        int4* ms = reinterpret_cast<int4*>(msh);
        for (int i = j; i < SS / 4; i += EE) { es[i] = eg[i]; ms[i] = mg[i]; }
    }
    __syncthreads();

    // Packed M column for state j: mp[i] = (exp(T[2i][j]), exp(T[2i+1][j])).
    // exp(-10000) underflows to exactly 0 — matches logsumexp semantics.
    u64 mp[EE / 2];
#pragma unroll
    for (int i = 0; i < EE / 2; i++)
        mp[i] = pack2(__expf(Tsh[(2 * i) * EE + j]), __expf(Tsh[(2 * i + 1) * EE + j]));

    const float* emb = em + (size_t)b * SS * EE;

    // t = 0: raw alpha, publish sum for deferred scale at t=1.
    float a    = __expf(Tsh[BOSs * EE + j] + emb[j]);
    float logC = 0.f;
    {
        float s = a;
#pragma unroll
        for (int o = 16; o > 0; o >>= 1) s += __shfl_xor_sync(0xffffffffu, s, o);
        if (lane == 0) red[w] = s;
        abuf[0][j] = a;
    }
    __syncthreads();

    float accS  = 0.f;        // path-score partial (thread j contributes when j==e_t)
    int   ep    = esh[0];     // raw previous entity
    int   lastE = ep;         // entity at last masked position
    int   cur   = 0;
    float em_next = emb[EE + j];

    for (int t = 1; t < SS; t++) {
        const float emv = em_next;
        if (t + 1 < SS) em_next = emb[(size_t)(t + 1) * EE + j];
        const int m = msh[t];
        const int e = esh[t];

        // v_j = sum_i a_i * M[i][j]  — packed over i: 16 LDS.128 + 32 FFMA2
        const ulonglong2* av = reinterpret_cast<const ulonglong2*>(abuf[cur]);
        u64 acc0 = 0ull, acc1 = 0ull, acc2 = 0ull, acc3 = 0ull;
#pragma unroll
        for (int k = 0; k < 16; k += 2) {
            const ulonglong2 p = av[k];
            const ulonglong2 q = av[k + 1];
            acc0 = ffma2(p.x, mp[2 * k + 0], acc0);
            acc1 = ffma2(p.y, mp[2 * k + 1], acc1);
            acc2 = ffma2(q.x, mp[2 * k + 2], acc2);
            acc3 = ffma2(q.y, mp[2 * k + 3], acc3);
        }
        const float2 vv = unpack2(fadd2(fadd2(acc0, acc1), fadd2(acc2, acc3)));
        float v = (vv.x + vv.y) * __expf(emv);

        // Deferred scale: first step after a norm step applies 1/S to everything.
        if ((t & (NE - 1)) == 1) {
            const float s    = red[0] + red[1];
            const float invS = 1.0f / s;
            logC += __logf(s);
            v *= invS;
            a = m ? v : a * invS;
        } else {
            a = m ? v : a;
        }

        // Fused path score: (em[t,e] + T[ep,e]) * mask[t]
        if (m) {
            if (j == e) accS += emv + Tsh[ep * EE + e];
            lastE = e;
        }
        ep = e;

        // Norm step: publish alpha-sum across the single end-of-step barrier.
        if ((t & (NE - 1)) == 0) {
            float s = a;
#pragma unroll
            for (int o = 16; o > 0; o >>= 1) s += __shfl_xor_sync(0xffffffffu, s, o);
            if (lane == 0) red[w] = s;
        }

        abuf[cur ^ 1][j] = a;
        __syncthreads();
        cur ^= 1;
    }

    // Finish: z = sum_j a_j * exp(T[j,EOS]); reduce z and score together.
    {
        float z = a * __expf(Tsh[j * EE + EOSs]);
        float s = accS;
#pragma unroll
        for (int o = 16; o > 0; o >>= 1) {
            z += __shfl_xor_sync(0xffffffffu, z, o);
            s += __shfl_xor_sync(0xffffffffu, s, o);
        }
        if (lane == 0) { redz[w] = z; reds[w] = s; }
        __syncthreads();
        if (j == 0) {
            const int e0 = esh[0];
            const float score = reds[0] + reds[1]
                              + Tsh[BOSs * EE + e0] + emb[e0]
                              + Tsh[lastE * EE + EOSs];
            const float logz = logC + __logf(redz[0] + redz[1]);
            g_val[b] = logz - score;
        }
    }
}

// ---------------------------------------------------------------------------
// Final reduction: nll = mean(log_z - score)
// ---------------------------------------------------------------------------
__global__ __launch_bounds__(512) void crf_reduce(float* __restrict__ out) {
    __shared__ float sh[BB];
    const int i = threadIdx.x;
    sh[i] = g_val[i];
    __syncthreads();
#pragma unroll
    for (int s = BB / 2; s > 0; s >>= 1) {
        if (i < s) sh[i] += sh[i + s];
        __syncthreads();
    }
    if (i == 0) out[0] = sh[0] / (float)BB;
}

extern "C" void kernel_launch(void* const* d_in, const int* in_sizes, int n_in,
                              void* d_out, int out_size) {
    const float* emissions   = (const float*)d_in[0];
    const float* transitions = (const float*)d_in[1];
    const int*   entities    = (const int*)d_in[2];
    const int*   mask        = (const int*)d_in[3];
    float* out               = (float*)d_out;

    crf_fused<<<BB, EE>>>(emissions, transitions, entities, mask);
    crf_reduce<<<1, BB>>>(out);
}